// round 10
// baseline (speedup 1.0000x reference)
#include <cuda_runtime.h>
#include <cuda_bf16.h>

// Problem constants
#define NN 50000
#define EE 800000
#define BB 2
#define TT 12
#define HH 16
#define T1 10          // T-2
#define T2 8           // T-4
#define BT1 (BB*T1)    // 20
#define ROW (BT1*HH)   // 320 floats per node
#define NB  ((NN + 255) / 256)   // scan blocks = 196

// Scratch (node-major layout: [n][b][t][h]).
// g_h1: holds A = h1@W0 + b after stage1, then h2 (in place) after agg.
// g_agg: holds Bw = h1@W1 after stage1 (gather source).
__device__ float g_h1[(size_t)NN * ROW];
__device__ float g_agg[(size_t)NN * ROW];
__device__ float g_deg[NN];
__device__ float g_dis[NN];
__device__ int   g_src[EE];
__device__ int   g_dst[EE];
__device__ int   g_cnt[NN];       // in-degree (by dst)
__device__ int   g_exc[NN];       // block-local exclusive scan
__device__ int   g_bsum[NB];      // per-block sums -> exclusive scanned
__device__ int   g_off[NN + 1];   // CSR row offsets (by dst)
__device__ int   g_fill[NN];      // bump cursors for scatter
__device__ int   g_esrc[EE];      // src sorted by dst
__device__ float g_enorm[EE];     // norm sorted by dst
__device__ int   g_oddnz;         // >0 => edge_index is int32; ==0 => int64

// Two identical repeat macros so they can nest.
#define RPT16A(M) M(0) M(1) M(2) M(3) M(4) M(5) M(6) M(7) \
                  M(8) M(9) M(10) M(11) M(12) M(13) M(14) M(15)
#define RPT16B(M) M(0) M(1) M(2) M(3) M(4) M(5) M(6) M(7) \
                  M(8) M(9) M(10) M(11) M(12) M(13) M(14) M(15)

// ---------------------------------------------------------------------------
__global__ void k_init() {
    int i = blockIdx.x * blockDim.x + threadIdx.x;
    if (i == 0) g_oddnz = 0;
    if (i < NN) { g_deg[i] = 0.f; g_cnt[i] = 0; }
}

// Detect dtype of edge_index (odd int32 words all zero <=> int64).
__global__ void k_detect(const int* __restrict__ w) {
    int i = blockIdx.x * blockDim.x + threadIdx.x;   // 4096 threads
    int v = w[2 * i + 1];
    unsigned ballot = __ballot_sync(0xFFFFFFFFu, v != 0);
    if ((threadIdx.x & 31) == 0 && ballot) atomicAdd(&g_oddnz, __popc(ballot));
}

// Unpack src/dst, accumulate weighted degree (by src) and in-count (by dst)
__global__ void k_convert(const int* __restrict__ w, const float* __restrict__ ew) {
    int e = blockIdx.x * blockDim.x + threadIdx.x;
    if (e >= EE) return;
    int src, dst;
    if (g_oddnz == 0) {  // int64
        src = w[2 * e];
        dst = w[2 * EE + 2 * e];
    } else {             // int32
        src = w[e];
        dst = w[EE + e];
    }
    g_src[e] = src;
    g_dst[e] = dst;
    atomicAdd(&g_deg[src], ew[e]);
    atomicAdd(&g_cnt[dst], 1);
}

// Scan pass 1: per-block exclusive scan of cnt, emit block sums
__global__ void k_scan_part() {
    __shared__ int s[256];
    int tid = threadIdx.x;
    int i = blockIdx.x * 256 + tid;
    int v = (i < NN) ? g_cnt[i] : 0;
    s[tid] = v;
    __syncthreads();
#pragma unroll
    for (int d = 1; d < 256; d <<= 1) {
        int t = (tid >= d) ? s[tid - d] : 0;
        __syncthreads();
        s[tid] += t;
        __syncthreads();
    }
    if (i < NN) g_exc[i] = s[tid] - v;
    if (tid == 255) g_bsum[blockIdx.x] = s[255];
}

// Scan pass 2: exclusive scan of block sums (single block)
__global__ void k_scan_top() {
    __shared__ int s[256];
    int tid = threadIdx.x;
    int v = (tid < NB) ? g_bsum[tid] : 0;
    s[tid] = v;
    __syncthreads();
#pragma unroll
    for (int d = 1; d < 256; d <<= 1) {
        int t = (tid >= d) ? s[tid - d] : 0;
        __syncthreads();
        s[tid] += t;
        __syncthreads();
    }
    if (tid < NB) g_bsum[tid] = s[tid] - v;
}

// Scan pass 3: final offsets + fill cursors + dis (merged)
__global__ void k_scan_add_dis() {
    int i = blockIdx.x * blockDim.x + threadIdx.x;
    if (i >= NN) return;
    int o = g_exc[i] + g_bsum[i >> 8];
    g_off[i] = o;
    g_fill[i] = o;
    if (i == 0) g_off[NN] = EE;
    float d = g_deg[i];
    g_dis[i] = (d > 0.f) ? rsqrtf(fmaxf(d, 1e-12f)) : 0.f;
}

// Scatter: CSR-sorted (src, norm) by dst
__global__ void k_scatter(const float* __restrict__ ew) {
    int e = blockIdx.x * blockDim.x + threadIdx.x;
    if (e >= EE) return;
    int src = g_src[e];
    int dst = g_dst[e];
    float nrm = -g_dis[src] * ew[e] * g_dis[dst];
    int pos = atomicAdd(&g_fill[dst], 1);
    g_esrc[pos] = src;
    g_enorm[pos] = nrm;
}

// Stage 1: temporal conv (GLU, 1->16) fused with the Cheb weight transforms.
// Writes A = h1@W0 + cb  -> g_h1   (to be combined in place by k_agg3)
//        Bw = h1@W1      -> g_agg  (gather source)
__global__ void k_stage1(const float* __restrict__ x,
                         const float* __restrict__ wP, const float* __restrict__ bP,
                         const float* __restrict__ wQ, const float* __restrict__ bQ,
                         const float* __restrict__ wR, const float* __restrict__ bR,
                         const float* __restrict__ cw, const float* __restrict__ cb) {
    __shared__ float sW0[256], sW1[256], sCB[16];
    {
        int tid = threadIdx.x;
        for (int i = tid; i < 256; i += blockDim.x) {
            sW0[i] = cw[i];
            sW1[i] = cw[256 + i];
        }
        if (tid < 16) sCB[tid] = cb[tid];
        __syncthreads();
    }
    int idx = blockIdx.x * blockDim.x + threadIdx.x;
    if (idx >= BT1 * NN) return;
    int n  = idx / BT1;
    int bt = idx - n * BT1;
    int b  = bt / T1;
    int t  = bt - b * T1;
    const float* xb = x + (size_t)(b * TT + t) * NN + n;
    float x0 = __ldg(xb);
    float x1 = __ldg(xb + NN);
    float x2 = __ldg(xb + 2 * NN);

#define S1H(h)                                                                  \
    float v##h;                                                                 \
    {                                                                           \
        float P = bP[h] + x0 * wP[h] + x1 * wP[16 + h] + x2 * wP[32 + h];       \
        float Q = bQ[h] + x0 * wQ[h] + x1 * wQ[16 + h] + x2 * wQ[32 + h];       \
        float R = bR[h] + x0 * wR[h] + x1 * wR[16 + h] + x2 * wR[32 + h];       \
        float s = 1.f / (1.f + __expf(-Q));                                     \
        v##h = fmaxf(fmaf(P, s, R), 0.f);                                       \
    }
    RPT16A(S1H)
#undef S1H

#define DECL(h) float a##h = sCB[h]; float g##h = 0.f;
    RPT16A(DECL)
#undef DECL

#define ACC(h) a##h = fmaf(vc, w0[h], a##h); g##h = fmaf(vc, w1[h], g##h);
#define STEP(c)                                                   \
    {                                                             \
        float vc = v##c;                                          \
        const float* w0 = &sW0[(c) * 16];                         \
        const float* w1 = &sW1[(c) * 16];                         \
        RPT16B(ACC)                                               \
    }
    RPT16A(STEP)
#undef STEP
#undef ACC

    float4* oa = (float4*)(g_h1 + (size_t)n * ROW + bt * HH);
    oa[0] = make_float4(a0, a1, a2, a3);
    oa[1] = make_float4(a4, a5, a6, a7);
    oa[2] = make_float4(a8, a9, a10, a11);
    oa[3] = make_float4(a12, a13, a14, a15);
    float4* og = (float4*)(g_agg + (size_t)n * ROW + bt * HH);
    og[0] = make_float4(g0, g1, g2, g3);
    og[1] = make_float4(g4, g5, g6, g7);
    og[2] = make_float4(g8, g9, g10, g11);
    og[3] = make_float4(g12, g13, g14, g15);
}

// CSR aggregation + Cheb combine epilogue.
// 16 threads per dst node; thread j owns float4 chunks {j, j+16, ..., j+64}.
// h2[n] = relu(A[n] + sum_{edges into n} norm * Bw[src]), written in place to g_h1.
__global__ __launch_bounds__(256) void k_agg3() {
    int gid = blockIdx.x * 256 + threadIdx.x;
    if (gid >= NN * 16) return;
    int n = gid >> 4;
    int j = gid & 15;
    int p   = g_off[n];
    int end = g_off[n + 1];
    float4 a0 = make_float4(0.f, 0.f, 0.f, 0.f);
    float4 a1 = a0, a2 = a0, a3 = a0, a4 = a0;
    for (; p < end; p++) {
        int   s = g_esrc[p];
        float w = g_enorm[p];
        const float4* src = (const float4*)(g_agg + (size_t)s * ROW) + j;
        float4 v0 = src[0], v1 = src[16], v2 = src[32], v3 = src[48], v4 = src[64];
        a0.x = fmaf(w, v0.x, a0.x); a0.y = fmaf(w, v0.y, a0.y);
        a0.z = fmaf(w, v0.z, a0.z); a0.w = fmaf(w, v0.w, a0.w);
        a1.x = fmaf(w, v1.x, a1.x); a1.y = fmaf(w, v1.y, a1.y);
        a1.z = fmaf(w, v1.z, a1.z); a1.w = fmaf(w, v1.w, a1.w);
        a2.x = fmaf(w, v2.x, a2.x); a2.y = fmaf(w, v2.y, a2.y);
        a2.z = fmaf(w, v2.z, a2.z); a2.w = fmaf(w, v2.w, a2.w);
        a3.x = fmaf(w, v3.x, a3.x); a3.y = fmaf(w, v3.y, a3.y);
        a3.z = fmaf(w, v3.z, a3.z); a3.w = fmaf(w, v3.w, a3.w);
        a4.x = fmaf(w, v4.x, a4.x); a4.y = fmaf(w, v4.y, a4.y);
        a4.z = fmaf(w, v4.z, a4.z); a4.w = fmaf(w, v4.w, a4.w);
    }
    float4* an = (float4*)(g_h1 + (size_t)n * ROW) + j;
#define EPI(i, acc)                                               \
    {                                                             \
        float4 t = an[16 * i];                                    \
        t.x = fmaxf(t.x + acc.x, 0.f);                            \
        t.y = fmaxf(t.y + acc.y, 0.f);                            \
        t.z = fmaxf(t.z + acc.z, 0.f);                            \
        t.w = fmaxf(t.w + acc.w, 0.f);                            \
        an[16 * i] = t;                                           \
    }
    EPI(0, a0) EPI(1, a1) EPI(2, a2) EPI(3, a3) EPI(4, a4)
#undef EPI
}

// Stage 4: temporal conv 2 (GLU 16->16) + mean over t + linear, fused.
// 4 threads per (b, n); thread p owns output channels 4p..4p+3.
// x window held as 12 float4 registers; weights read as LDS.128.
__global__ __launch_bounds__(256) void k_stage4(
    const float* __restrict__ wP, const float* __restrict__ bP,
    const float* __restrict__ wQ, const float* __restrict__ bQ,
    const float* __restrict__ wR, const float* __restrict__ bR,
    const float* __restrict__ lw, const float* __restrict__ lb,
    float* __restrict__ out) {
    __shared__ float sWP[768], sWQ[768], sWR[768];  // [k][c][h], h fastest
    __shared__ float sBP[16], sBQ[16], sBR[16], sLW[32], sLB[2];
    int tid = threadIdx.x;
    for (int i = tid; i < 768; i += 256) {
        sWP[i] = wP[i];
        sWQ[i] = wQ[i];
        sWR[i] = wR[i];
    }
    if (tid < 16) { sBP[tid] = bP[tid]; sBQ[tid] = bQ[tid]; sBR[tid] = bR[tid]; }
    if (tid < 32) sLW[tid] = lw[tid];
    if (tid < 2)  sLB[tid] = lb[tid];
    __syncthreads();

    int gid = blockIdx.x * 256 + tid;        // BB*NN*4 = 400000 threads
    if (gid >= BB * NN * 4) return;
    int g = gid >> 2;                        // (b, n) group
    int p = gid & 3;                         // channel quad
    int b = g / NN;
    int n = g - b * NN;
    const float4* row4 = (const float4*)(g_h1 + (size_t)n * ROW + b * (T1 * HH)); // 40 float4

    // Per-quad weight pointers: entry (k*16+c) is a float4 of channels 4p..4p+3.
    const float4* wP4 = (const float4*)sWP + p;
    const float4* wQ4 = (const float4*)sWQ + p;
    const float4* wR4 = (const float4*)sWR + p;
    float4 bp = ((const float4*)sBP)[p];
    float4 bq = ((const float4*)sBQ)[p];
    float4 br = ((const float4*)sBR)[p];

    float m0 = 0.f, m1 = 0.f, m2 = 0.f, m3 = 0.f;

#define DOONE(kc, xv)                                             \
    {                                                             \
        float4 wp = wP4[(kc) * 4];                                \
        float4 wq = wQ4[(kc) * 4];                                \
        float4 wr = wR4[(kc) * 4];                                \
        P0 = fmaf(xv, wp.x, P0); P1 = fmaf(xv, wp.y, P1);         \
        P2 = fmaf(xv, wp.z, P2); P3 = fmaf(xv, wp.w, P3);         \
        Q0 = fmaf(xv, wq.x, Q0); Q1 = fmaf(xv, wq.y, Q1);         \
        Q2 = fmaf(xv, wq.z, Q2); Q3 = fmaf(xv, wq.w, Q3);         \
        R0 = fmaf(xv, wr.x, R0); R1 = fmaf(xv, wr.y, R1);         \
        R2 = fmaf(xv, wr.z, R2); R3 = fmaf(xv, wr.w, R3);         \
    }
#define DO4(kcbase, V) DOONE(kcbase, V.x) DOONE((kcbase)+1, V.y) \
                       DOONE((kcbase)+2, V.z) DOONE((kcbase)+3, V.w)

#pragma unroll 1
    for (int t = 0; t < T2; t++) {
        const float4* w4 = row4 + t * 4;
        float4 xa0 = w4[0],  xa1 = w4[1],  xa2 = w4[2],  xa3 = w4[3];
        float4 xb0 = w4[4],  xb1 = w4[5],  xb2 = w4[6],  xb3 = w4[7];
        float4 xc0 = w4[8],  xc1 = w4[9],  xc2 = w4[10], xc3 = w4[11];
        float P0 = bp.x, P1 = bp.y, P2 = bp.z, P3 = bp.w;
        float Q0 = bq.x, Q1 = bq.y, Q2 = bq.z, Q3 = bq.w;
        float R0 = br.x, R1 = br.y, R2 = br.z, R3 = br.w;
        DO4(0,  xa0) DO4(4,  xa1) DO4(8,  xa2) DO4(12, xa3)
        DO4(16, xb0) DO4(20, xb1) DO4(24, xb2) DO4(28, xb3)
        DO4(32, xc0) DO4(36, xc1) DO4(40, xc2) DO4(44, xc3)
        float s0 = 1.f / (1.f + __expf(-Q0));
        float s1 = 1.f / (1.f + __expf(-Q1));
        float s2 = 1.f / (1.f + __expf(-Q2));
        float s3 = 1.f / (1.f + __expf(-Q3));
        m0 += fmaxf(fmaf(P0, s0, R0), 0.f);
        m1 += fmaxf(fmaf(P1, s1, R1), 0.f);
        m2 += fmaxf(fmaf(P2, s2, R2), 0.f);
        m3 += fmaxf(fmaf(P3, s3, R3), 0.f);
    }
#undef DO4
#undef DOONE

    m0 *= 0.125f; m1 *= 0.125f; m2 *= 0.125f; m3 *= 0.125f;
    int hb = 4 * p;
    float o0 = m0 * sLW[2 * hb]     + m1 * sLW[2 * hb + 2]
             + m2 * sLW[2 * hb + 4] + m3 * sLW[2 * hb + 6];
    float o1 = m0 * sLW[2 * hb + 1] + m1 * sLW[2 * hb + 3]
             + m2 * sLW[2 * hb + 5] + m3 * sLW[2 * hb + 7];
    o0 += __shfl_down_sync(0xFFFFFFFFu, o0, 2, 4);
    o1 += __shfl_down_sync(0xFFFFFFFFu, o1, 2, 4);
    o0 += __shfl_down_sync(0xFFFFFFFFu, o0, 1, 4);
    o1 += __shfl_down_sync(0xFFFFFFFFu, o1, 1, 4);
    if (p == 0) ((float2*)out)[g] = make_float2(o0 + sLB[0], o1 + sLB[1]);
}

// ---------------------------------------------------------------------------
extern "C" void kernel_launch(void* const* d_in, const int* in_sizes, int n_in,
                              void* d_out, int out_size) {
    const float* x   = (const float*)d_in[0];
    const int*   eiw = (const int*)d_in[1];   // edge_index words (int32 or int64)
    const float* ew  = (const float*)d_in[2];
    const float* tc1Pw = (const float*)d_in[3];
    const float* tc1Pb = (const float*)d_in[4];
    const float* tc1Qw = (const float*)d_in[5];
    const float* tc1Qb = (const float*)d_in[6];
    const float* tc1Rw = (const float*)d_in[7];
    const float* tc1Rb = (const float*)d_in[8];
    const float* tc2Pw = (const float*)d_in[9];
    const float* tc2Pb = (const float*)d_in[10];
    const float* tc2Qw = (const float*)d_in[11];
    const float* tc2Qb = (const float*)d_in[12];
    const float* tc2Rw = (const float*)d_in[13];
    const float* tc2Rb = (const float*)d_in[14];
    const float* chebw = (const float*)d_in[15];
    const float* chebb = (const float*)d_in[16];
    const float* linw  = (const float*)d_in[17];
    const float* linb  = (const float*)d_in[18];
    float* out = (float*)d_out;

    k_init<<<(NN + 255) / 256, 256>>>();
    k_detect<<<16, 256>>>(eiw);
    k_convert<<<(EE + 255) / 256, 256>>>(eiw, ew);
    k_scan_part<<<NB, 256>>>();
    k_scan_top<<<1, 256>>>();
    k_scan_add_dis<<<(NN + 255) / 256, 256>>>();
    k_scatter<<<(EE + 255) / 256, 256>>>(ew);
    k_stage1<<<(BT1 * NN + 255) / 256, 256>>>(x, tc1Pw, tc1Pb, tc1Qw, tc1Qb, tc1Rw, tc1Rb,
                                              chebw, chebb);
    k_agg3<<<(NN * 16 + 255) / 256, 256>>>();
    k_stage4<<<(BB * NN * 4 + 255) / 256, 256>>>(tc2Pw, tc2Pb, tc2Qw, tc2Qb, tc2Rw, tc2Rb,
                                                 linw, linb, out);
}

// round 12
// speedup vs baseline: 2.6899x; 2.6899x over previous
#include <cuda_runtime.h>
#include <cuda_bf16.h>

// Problem constants
#define NN 50000
#define EE 800000
#define BB 2
#define TT 12
#define HH 16
#define T1 10          // T-2
#define T2 8           // T-4
#define BT1 (BB*T1)    // 20
#define ROW (BT1*HH)   // 320 floats per node
#define NB  ((NN + 255) / 256)   // scan blocks = 196

// Scratch (node-major layout: [n][b][t][h]).
// g_h1: holds A = h1@W0 + b after stage1, then h2 (in place) after agg.
// g_agg: holds Bw = h1@W1 after stage1 (gather source).
__device__ float g_h1[(size_t)NN * ROW];
__device__ float g_agg[(size_t)NN * ROW];
__device__ float g_deg[NN];
__device__ float g_dis[NN];
__device__ int   g_src[EE];
__device__ int   g_dst[EE];
__device__ int   g_cnt[NN];       // in-degree (by dst)
__device__ int   g_exc[NN];       // block-local exclusive scan
__device__ int   g_bsum[NB];      // per-block sums -> exclusive scanned
__device__ int   g_off[NN + 1];   // CSR row offsets (by dst)
__device__ int   g_fill[NN];      // bump cursors for scatter
__device__ int2  g_epack[EE];     // {src, norm-bits} sorted by dst
__device__ int   g_oddnz;         // >0 => edge_index is int32; ==0 => int64

// Two identical repeat macros so they can nest.
#define RPT16A(M) M(0) M(1) M(2) M(3) M(4) M(5) M(6) M(7) \
                  M(8) M(9) M(10) M(11) M(12) M(13) M(14) M(15)
#define RPT16B(M) M(0) M(1) M(2) M(3) M(4) M(5) M(6) M(7) \
                  M(8) M(9) M(10) M(11) M(12) M(13) M(14) M(15)

// ---------------------------------------------------------------------------
__global__ void k_init() {
    int i = blockIdx.x * blockDim.x + threadIdx.x;
    if (i == 0) g_oddnz = 0;
    if (i < NN) { g_deg[i] = 0.f; g_cnt[i] = 0; }
}

// Detect dtype of edge_index (odd int32 words all zero <=> int64).
__global__ void k_detect(const int* __restrict__ w) {
    int i = blockIdx.x * blockDim.x + threadIdx.x;   // 4096 threads
    int v = w[2 * i + 1];
    unsigned ballot = __ballot_sync(0xFFFFFFFFu, v != 0);
    if ((threadIdx.x & 31) == 0 && ballot) atomicAdd(&g_oddnz, __popc(ballot));
}

// Unpack src/dst, accumulate weighted degree (by src) and in-count (by dst)
__global__ void k_convert(const int* __restrict__ w, const float* __restrict__ ew) {
    int e = blockIdx.x * blockDim.x + threadIdx.x;
    if (e >= EE) return;
    int src, dst;
    if (g_oddnz == 0) {  // int64
        src = w[2 * e];
        dst = w[2 * EE + 2 * e];
    } else {             // int32
        src = w[e];
        dst = w[EE + e];
    }
    g_src[e] = src;
    g_dst[e] = dst;
    atomicAdd(&g_deg[src], ew[e]);
    atomicAdd(&g_cnt[dst], 1);
}

// Scan pass 1: per-block exclusive scan of cnt, emit block sums
__global__ void k_scan_part() {
    __shared__ int s[256];
    int tid = threadIdx.x;
    int i = blockIdx.x * 256 + tid;
    int v = (i < NN) ? g_cnt[i] : 0;
    s[tid] = v;
    __syncthreads();
#pragma unroll
    for (int d = 1; d < 256; d <<= 1) {
        int t = (tid >= d) ? s[tid - d] : 0;
        __syncthreads();
        s[tid] += t;
        __syncthreads();
    }
    if (i < NN) g_exc[i] = s[tid] - v;
    if (tid == 255) g_bsum[blockIdx.x] = s[255];
}

// Scan pass 2: exclusive scan of block sums (single block)
__global__ void k_scan_top() {
    __shared__ int s[256];
    int tid = threadIdx.x;
    int v = (tid < NB) ? g_bsum[tid] : 0;
    s[tid] = v;
    __syncthreads();
#pragma unroll
    for (int d = 1; d < 256; d <<= 1) {
        int t = (tid >= d) ? s[tid - d] : 0;
        __syncthreads();
        s[tid] += t;
        __syncthreads();
    }
    if (tid < NB) g_bsum[tid] = s[tid] - v;
}

// Scan pass 3: final offsets + fill cursors + dis (merged)
__global__ void k_scan_add_dis() {
    int i = blockIdx.x * blockDim.x + threadIdx.x;
    if (i >= NN) return;
    int o = g_exc[i] + g_bsum[i >> 8];
    g_off[i] = o;
    g_fill[i] = o;
    if (i == 0) g_off[NN] = EE;
    float d = g_deg[i];
    g_dis[i] = (d > 0.f) ? rsqrtf(fmaxf(d, 1e-12f)) : 0.f;
}

// Scatter: CSR-sorted packed (src, norm) by dst
__global__ void k_scatter(const float* __restrict__ ew) {
    int e = blockIdx.x * blockDim.x + threadIdx.x;
    if (e >= EE) return;
    int src = g_src[e];
    int dst = g_dst[e];
    float nrm = -g_dis[src] * ew[e] * g_dis[dst];
    int pos = atomicAdd(&g_fill[dst], 1);
    g_epack[pos] = make_int2(src, __float_as_int(nrm));
}

// Stage 1: temporal conv (GLU, 1->16) fused with the Cheb weight transforms.
// Writes A = h1@W0 + cb  -> g_h1   (to be combined in place by k_agg3)
//        Bw = h1@W1      -> g_agg  (gather source)
__global__ void k_stage1(const float* __restrict__ x,
                         const float* __restrict__ wP, const float* __restrict__ bP,
                         const float* __restrict__ wQ, const float* __restrict__ bQ,
                         const float* __restrict__ wR, const float* __restrict__ bR,
                         const float* __restrict__ cw, const float* __restrict__ cb) {
    __shared__ float sW0[256], sW1[256], sCB[16];
    {
        int tid = threadIdx.x;
        for (int i = tid; i < 256; i += blockDim.x) {
            sW0[i] = cw[i];
            sW1[i] = cw[256 + i];
        }
        if (tid < 16) sCB[tid] = cb[tid];
        __syncthreads();
    }
    int idx = blockIdx.x * blockDim.x + threadIdx.x;
    if (idx >= BT1 * NN) return;
    int n  = idx / BT1;
    int bt = idx - n * BT1;
    int b  = bt / T1;
    int t  = bt - b * T1;
    const float* xb = x + (size_t)(b * TT + t) * NN + n;
    float x0 = __ldg(xb);
    float x1 = __ldg(xb + NN);
    float x2 = __ldg(xb + 2 * NN);

#define S1H(h)                                                                  \
    float v##h;                                                                 \
    {                                                                           \
        float P = bP[h] + x0 * wP[h] + x1 * wP[16 + h] + x2 * wP[32 + h];       \
        float Q = bQ[h] + x0 * wQ[h] + x1 * wQ[16 + h] + x2 * wQ[32 + h];       \
        float R = bR[h] + x0 * wR[h] + x1 * wR[16 + h] + x2 * wR[32 + h];       \
        float s = 1.f / (1.f + __expf(-Q));                                     \
        v##h = fmaxf(fmaf(P, s, R), 0.f);                                       \
    }
    RPT16A(S1H)
#undef S1H

#define DECL(h) float a##h = sCB[h]; float g##h = 0.f;
    RPT16A(DECL)
#undef DECL

#define ACC(h) a##h = fmaf(vc, w0[h], a##h); g##h = fmaf(vc, w1[h], g##h);
#define STEP(c)                                                   \
    {                                                             \
        float vc = v##c;                                          \
        const float* w0 = &sW0[(c) * 16];                         \
        const float* w1 = &sW1[(c) * 16];                         \
        RPT16B(ACC)                                               \
    }
    RPT16A(STEP)
#undef STEP
#undef ACC

    float4* oa = (float4*)(g_h1 + (size_t)n * ROW + bt * HH);
    oa[0] = make_float4(a0, a1, a2, a3);
    oa[1] = make_float4(a4, a5, a6, a7);
    oa[2] = make_float4(a8, a9, a10, a11);
    oa[3] = make_float4(a12, a13, a14, a15);
    float4* og = (float4*)(g_agg + (size_t)n * ROW + bt * HH);
    og[0] = make_float4(g0, g1, g2, g3);
    og[1] = make_float4(g4, g5, g6, g7);
    og[2] = make_float4(g8, g9, g10, g11);
    og[3] = make_float4(g12, g13, g14, g15);
}

// CSR aggregation + Cheb combine epilogue.  (champion mapping: 8 threads/node)
// Thread j owns float4 chunks {j, j+8, ..., j+72}. Edge records prefetched.
// h2[n] = relu(A[n] + sum_{edges into n} norm * Bw[src]), written in place to g_h1.
__global__ __launch_bounds__(256) void k_agg3() {
    int gid = blockIdx.x * 256 + threadIdx.x;
    if (gid >= NN * 8) return;
    int n = gid >> 3;
    int j = gid & 7;
    int p   = g_off[n];
    int end = g_off[n + 1];
    float4 acc[10];
#pragma unroll
    for (int i = 0; i < 10; i++) acc[i] = make_float4(0.f, 0.f, 0.f, 0.f);
    if (p < end) {
        int2 ed = g_epack[p];
        for (;;) {
            int   s = ed.x;
            float w = __int_as_float(ed.y);
            p++;
            bool more = (p < end);
            if (more) ed = g_epack[p];           // prefetch next record
            const float4* src = (const float4*)(g_agg + (size_t)s * ROW) + j;
#pragma unroll
            for (int i = 0; i < 10; i++) {
                float4 v = src[8 * i];
                acc[i].x = fmaf(w, v.x, acc[i].x);
                acc[i].y = fmaf(w, v.y, acc[i].y);
                acc[i].z = fmaf(w, v.z, acc[i].z);
                acc[i].w = fmaf(w, v.w, acc[i].w);
            }
            if (!more) break;
        }
    }
    float4* an = (float4*)(g_h1 + (size_t)n * ROW) + j;
#pragma unroll
    for (int i = 0; i < 10; i++) {
        float4 a = an[8 * i];
        a.x = fmaxf(a.x + acc[i].x, 0.f);
        a.y = fmaxf(a.y + acc[i].y, 0.f);
        a.z = fmaxf(a.z + acc[i].z, 0.f);
        a.w = fmaxf(a.w + acc[i].w, 0.f);
        an[8 * i] = a;
    }
}

// Stage 4: temporal conv 2 (GLU 16->16) + mean over t + linear, fused.
// Champion mapping: 8 threads per (b, n); thread p owns channels 2p, 2p+1.
// Delta vs champion: x window loaded as 12 float4 (LDG.128) per t.
__global__ __launch_bounds__(256) void k_stage4(
    const float* __restrict__ wP, const float* __restrict__ bP,
    const float* __restrict__ wQ, const float* __restrict__ bQ,
    const float* __restrict__ wR, const float* __restrict__ bR,
    const float* __restrict__ lw, const float* __restrict__ lb,
    float* __restrict__ out) {
    __shared__ float sWP[768], sWQ[768], sWR[768];  // [k][c][h]
    __shared__ float sBP[16], sBQ[16], sBR[16], sLW[32], sLB[2];
    int tid = threadIdx.x;
    for (int i = tid; i < 768; i += 256) {
        sWP[i] = wP[i];
        sWQ[i] = wQ[i];
        sWR[i] = wR[i];
    }
    if (tid < 16) { sBP[tid] = bP[tid]; sBQ[tid] = bQ[tid]; sBR[tid] = bR[tid]; }
    if (tid < 32) sLW[tid] = lw[tid];
    if (tid < 2)  sLB[tid] = lb[tid];
    __syncthreads();

    int gid = blockIdx.x * 256 + tid;        // exactly BB*NN*8 = 800000 threads
    int g = gid >> 3;                        // (b, n) group
    int p = gid & 7;                         // channel pair
    int b = g / NN;
    int n = g - b * NN;
    const float* row = g_h1 + (size_t)n * ROW + b * (T1 * HH);
    int h0 = 2 * p, h1 = 2 * p + 1;

    float bp0 = sBP[h0], bp1 = sBP[h1];
    float bq0 = sBQ[h0], bq1 = sBQ[h1];
    float br0 = sBR[h0], br1 = sBR[h1];
    float m0 = 0.f, m1 = 0.f;

#define FMA6(xv, kc)                                              \
    {                                                             \
        P0 = fmaf(xv, sWP[(kc) * 16 + h0], P0);                   \
        P1 = fmaf(xv, sWP[(kc) * 16 + h1], P1);                   \
        Q0 = fmaf(xv, sWQ[(kc) * 16 + h0], Q0);                   \
        Q1 = fmaf(xv, sWQ[(kc) * 16 + h1], Q1);                   \
        R0 = fmaf(xv, sWR[(kc) * 16 + h0], R0);                   \
        R1 = fmaf(xv, sWR[(kc) * 16 + h1], R1);                   \
    }
#define FMA6x4(base, V) FMA6(V.x, base) FMA6(V.y, (base)+1)       \
                        FMA6(V.z, (base)+2) FMA6(V.w, (base)+3)

#pragma unroll 1
    for (int t = 0; t < T2; t++) {
        const float4* x4 = (const float4*)(row + t * HH);  // 48 contiguous floats
        float4 v0 = x4[0], v1 = x4[1], v2  = x4[2],  v3  = x4[3];
        float4 v4 = x4[4], v5 = x4[5], v6  = x4[6],  v7  = x4[7];
        float4 v8 = x4[8], v9 = x4[9], v10 = x4[10], v11 = x4[11];
        float P0 = bp0, P1 = bp1, Q0 = bq0, Q1 = bq1, R0 = br0, R1 = br1;
        FMA6x4(0,  v0) FMA6x4(4,  v1) FMA6x4(8,  v2)  FMA6x4(12, v3)
        FMA6x4(16, v4) FMA6x4(20, v5) FMA6x4(24, v6)  FMA6x4(28, v7)
        FMA6x4(32, v8) FMA6x4(36, v9) FMA6x4(40, v10) FMA6x4(44, v11)
        float s0 = 1.f / (1.f + __expf(-Q0));
        float s1 = 1.f / (1.f + __expf(-Q1));
        m0 += fmaxf(fmaf(P0, s0, R0), 0.f);
        m1 += fmaxf(fmaf(P1, s1, R1), 0.f);
    }
#undef FMA6x4
#undef FMA6

    m0 *= 0.125f;
    m1 *= 0.125f;
    float o0 = m0 * sLW[2 * h0]     + m1 * sLW[2 * h1];
    float o1 = m0 * sLW[2 * h0 + 1] + m1 * sLW[2 * h1 + 1];
#pragma unroll
    for (int s = 4; s > 0; s >>= 1) {
        o0 += __shfl_down_sync(0xFFFFFFFFu, o0, s, 8);
        o1 += __shfl_down_sync(0xFFFFFFFFu, o1, s, 8);
    }
    if (p == 0) ((float2*)out)[g] = make_float2(o0 + sLB[0], o1 + sLB[1]);
}

// ---------------------------------------------------------------------------
extern "C" void kernel_launch(void* const* d_in, const int* in_sizes, int n_in,
                              void* d_out, int out_size) {
    const float* x   = (const float*)d_in[0];
    const int*   eiw = (const int*)d_in[1];   // edge_index words (int32 or int64)
    const float* ew  = (const float*)d_in[2];
    const float* tc1Pw = (const float*)d_in[3];
    const float* tc1Pb = (const float*)d_in[4];
    const float* tc1Qw = (const float*)d_in[5];
    const float* tc1Qb = (const float*)d_in[6];
    const float* tc1Rw = (const float*)d_in[7];
    const float* tc1Rb = (const float*)d_in[8];
    const float* tc2Pw = (const float*)d_in[9];
    const float* tc2Pb = (const float*)d_in[10];
    const float* tc2Qw = (const float*)d_in[11];
    const float* tc2Qb = (const float*)d_in[12];
    const float* tc2Rw = (const float*)d_in[13];
    const float* tc2Rb = (const float*)d_in[14];
    const float* chebw = (const float*)d_in[15];
    const float* chebb = (const float*)d_in[16];
    const float* linw  = (const float*)d_in[17];
    const float* linb  = (const float*)d_in[18];
    float* out = (float*)d_out;

    k_init<<<(NN + 255) / 256, 256>>>();
    k_detect<<<16, 256>>>(eiw);
    k_convert<<<(EE + 255) / 256, 256>>>(eiw, ew);
    k_scan_part<<<NB, 256>>>();
    k_scan_top<<<1, 256>>>();
    k_scan_add_dis<<<(NN + 255) / 256, 256>>>();
    k_scatter<<<(EE + 255) / 256, 256>>>(ew);
    k_stage1<<<(BT1 * NN + 255) / 256, 256>>>(x, tc1Pw, tc1Pb, tc1Qw, tc1Qb, tc1Rw, tc1Rb,
                                              chebw, chebb);
    k_agg3<<<(NN * 8 + 255) / 256, 256>>>();
    k_stage4<<<(BB * NN * 8) / 256, 256>>>(tc2Pw, tc2Pb, tc2Qw, tc2Qb, tc2Rw, tc2Rb,
                                           linw, linb, out);
}

// round 15
// speedup vs baseline: 3.1701x; 1.1785x over previous
#include <cuda_runtime.h>
#include <cuda_fp16.h>
#include <cuda_bf16.h>

// Problem constants
#define NN 50000
#define EE 800000
#define BB 2
#define TT 12
#define HH 16
#define T1 10          // T-2
#define T2 8           // T-4
#define BT1 (BB*T1)    // 20
#define ROW (BT1*HH)   // 320 floats per node
#define NB  ((NN + 255) / 256)   // scan blocks = 196

// Bit-cast helpers (the named intrinsics don't exist in cuda_fp16.h)
__device__ __forceinline__ unsigned h2_as_u32(__half2 h) {
    return *reinterpret_cast<unsigned*>(&h);
}
__device__ __forceinline__ __half2 u32_as_h2(unsigned u) {
    return *reinterpret_cast<__half2*>(&u);
}

// Scratch (node-major layout: [n][b][t][h]).
// g_h1: holds A = h1@W0 + b after stage1, then h2 (in place) after agg.
// g_bwh: holds Bw = h1@W1 in fp16 after stage1 (gather source, 32 MB, L2-resident).
__device__ float  g_h1[(size_t)NN * ROW];
__device__ __half g_bwh[(size_t)NN * ROW];
__device__ float  g_deg[NN];
__device__ float  g_dis[NN];
__device__ int    g_src[EE];
__device__ int    g_dst[EE];
__device__ int    g_cnt[NN];       // in-degree (by dst)
__device__ int    g_exc[NN];       // block-local exclusive scan
__device__ int    g_bsum[NB];      // per-block sums -> exclusive scanned
__device__ int    g_off[NN + 1];   // CSR row offsets (by dst)
__device__ int    g_fill[NN];      // bump cursors for scatter
__device__ int2   g_epack[EE];     // {src, norm-bits} sorted by dst
__device__ int    g_oddnz;         // >0 => edge_index is int32; ==0 => int64

// Two identical repeat macros so they can nest.
#define RPT16A(M) M(0) M(1) M(2) M(3) M(4) M(5) M(6) M(7) \
                  M(8) M(9) M(10) M(11) M(12) M(13) M(14) M(15)
#define RPT16B(M) M(0) M(1) M(2) M(3) M(4) M(5) M(6) M(7) \
                  M(8) M(9) M(10) M(11) M(12) M(13) M(14) M(15)

// ---------------------------------------------------------------------------
__global__ void k_init() {
    int i = blockIdx.x * blockDim.x + threadIdx.x;
    if (i == 0) g_oddnz = 0;
    if (i < NN) { g_deg[i] = 0.f; g_cnt[i] = 0; }
}

// Detect dtype of edge_index (odd int32 words all zero <=> int64).
__global__ void k_detect(const int* __restrict__ w) {
    int i = blockIdx.x * blockDim.x + threadIdx.x;   // 4096 threads
    int v = w[2 * i + 1];
    unsigned ballot = __ballot_sync(0xFFFFFFFFu, v != 0);
    if ((threadIdx.x & 31) == 0 && ballot) atomicAdd(&g_oddnz, __popc(ballot));
}

// Unpack src/dst, accumulate weighted degree (by src) and in-count (by dst)
__global__ void k_convert(const int* __restrict__ w, const float* __restrict__ ew) {
    int e = blockIdx.x * blockDim.x + threadIdx.x;
    if (e >= EE) return;
    int src, dst;
    if (g_oddnz == 0) {  // int64
        src = w[2 * e];
        dst = w[2 * EE + 2 * e];
    } else {             // int32
        src = w[e];
        dst = w[EE + e];
    }
    g_src[e] = src;
    g_dst[e] = dst;
    atomicAdd(&g_deg[src], ew[e]);
    atomicAdd(&g_cnt[dst], 1);
}

// Scan pass 1: per-block exclusive scan of cnt, emit block sums
__global__ void k_scan_part() {
    __shared__ int s[256];
    int tid = threadIdx.x;
    int i = blockIdx.x * 256 + tid;
    int v = (i < NN) ? g_cnt[i] : 0;
    s[tid] = v;
    __syncthreads();
#pragma unroll
    for (int d = 1; d < 256; d <<= 1) {
        int t = (tid >= d) ? s[tid - d] : 0;
        __syncthreads();
        s[tid] += t;
        __syncthreads();
    }
    if (i < NN) g_exc[i] = s[tid] - v;
    if (tid == 255) g_bsum[blockIdx.x] = s[255];
}

// Scan pass 2: exclusive scan of block sums (single block)
__global__ void k_scan_top() {
    __shared__ int s[256];
    int tid = threadIdx.x;
    int v = (tid < NB) ? g_bsum[tid] : 0;
    s[tid] = v;
    __syncthreads();
#pragma unroll
    for (int d = 1; d < 256; d <<= 1) {
        int t = (tid >= d) ? s[tid - d] : 0;
        __syncthreads();
        s[tid] += t;
        __syncthreads();
    }
    if (tid < NB) g_bsum[tid] = s[tid] - v;
}

// Scan pass 3: final offsets + fill cursors + dis (merged)
__global__ void k_scan_add_dis() {
    int i = blockIdx.x * blockDim.x + threadIdx.x;
    if (i >= NN) return;
    int o = g_exc[i] + g_bsum[i >> 8];
    g_off[i] = o;
    g_fill[i] = o;
    if (i == 0) g_off[NN] = EE;
    float d = g_deg[i];
    g_dis[i] = (d > 0.f) ? rsqrtf(fmaxf(d, 1e-12f)) : 0.f;
}

// Scatter: CSR-sorted packed (src, norm) by dst
__global__ void k_scatter(const float* __restrict__ ew) {
    int e = blockIdx.x * blockDim.x + threadIdx.x;
    if (e >= EE) return;
    int src = g_src[e];
    int dst = g_dst[e];
    float nrm = -g_dis[src] * ew[e] * g_dis[dst];
    int pos = atomicAdd(&g_fill[dst], 1);
    g_epack[pos] = make_int2(src, __float_as_int(nrm));
}

// Stage 1: temporal conv (GLU, 1->16) fused with the Cheb weight transforms.
// Writes A = h1@W0 + cb  -> g_h1   (fp32; combined in place by k_agg3)
//        Bw = h1@W1      -> g_bwh  (fp16 gather payload)
__global__ void k_stage1(const float* __restrict__ x,
                         const float* __restrict__ wP, const float* __restrict__ bP,
                         const float* __restrict__ wQ, const float* __restrict__ bQ,
                         const float* __restrict__ wR, const float* __restrict__ bR,
                         const float* __restrict__ cw, const float* __restrict__ cb) {
    __shared__ float sW0[256], sW1[256], sCB[16];
    {
        int tid = threadIdx.x;
        for (int i = tid; i < 256; i += blockDim.x) {
            sW0[i] = cw[i];
            sW1[i] = cw[256 + i];
        }
        if (tid < 16) sCB[tid] = cb[tid];
        __syncthreads();
    }
    int idx = blockIdx.x * blockDim.x + threadIdx.x;
    if (idx >= BT1 * NN) return;
    int n  = idx / BT1;
    int bt = idx - n * BT1;
    int b  = bt / T1;
    int t  = bt - b * T1;
    const float* xb = x + (size_t)(b * TT + t) * NN + n;
    float x0 = __ldg(xb);
    float x1 = __ldg(xb + NN);
    float x2 = __ldg(xb + 2 * NN);

#define S1H(h)                                                                  \
    float v##h;                                                                 \
    {                                                                           \
        float P = bP[h] + x0 * wP[h] + x1 * wP[16 + h] + x2 * wP[32 + h];       \
        float Q = bQ[h] + x0 * wQ[h] + x1 * wQ[16 + h] + x2 * wQ[32 + h];       \
        float R = bR[h] + x0 * wR[h] + x1 * wR[16 + h] + x2 * wR[32 + h];       \
        float s = 1.f / (1.f + __expf(-Q));                                     \
        v##h = fmaxf(fmaf(P, s, R), 0.f);                                       \
    }
    RPT16A(S1H)
#undef S1H

#define DECL(h) float a##h = sCB[h]; float g##h = 0.f;
    RPT16A(DECL)
#undef DECL

#define ACC(h) a##h = fmaf(vc, w0[h], a##h); g##h = fmaf(vc, w1[h], g##h);
#define STEP(c)                                                   \
    {                                                             \
        float vc = v##c;                                          \
        const float* w0 = &sW0[(c) * 16];                         \
        const float* w1 = &sW1[(c) * 16];                         \
        RPT16B(ACC)                                               \
    }
    RPT16A(STEP)
#undef STEP
#undef ACC

    float4* oa = (float4*)(g_h1 + (size_t)n * ROW + bt * HH);
    oa[0] = make_float4(a0, a1, a2, a3);
    oa[1] = make_float4(a4, a5, a6, a7);
    oa[2] = make_float4(a8, a9, a10, a11);
    oa[3] = make_float4(a12, a13, a14, a15);

    // Pack Bw to fp16: 16 halves = 2 uint4 stores.
    unsigned p0 = h2_as_u32(__floats2half2_rn(g0,  g1));
    unsigned p1 = h2_as_u32(__floats2half2_rn(g2,  g3));
    unsigned p2 = h2_as_u32(__floats2half2_rn(g4,  g5));
    unsigned p3 = h2_as_u32(__floats2half2_rn(g6,  g7));
    unsigned p4 = h2_as_u32(__floats2half2_rn(g8,  g9));
    unsigned p5 = h2_as_u32(__floats2half2_rn(g10, g11));
    unsigned p6 = h2_as_u32(__floats2half2_rn(g12, g13));
    unsigned p7 = h2_as_u32(__floats2half2_rn(g14, g15));
    uint4* og = (uint4*)(g_bwh + (size_t)n * ROW + bt * HH);  // uint4 idx n*40 + bt*2
    og[0] = make_uint4(p0, p1, p2, p3);
    og[1] = make_uint4(p4, p5, p6, p7);
}

// CSR aggregation + Cheb combine epilogue.  8 threads per dst node.
// Row = 320 halves = 40 uint4; thread j owns uint4 chunks {j, j+8, ..., j+32} (5).
// fp16 payload unpacked to fp32 and accumulated in fp32.
// h2[n] = relu(A[n] + sum norm * Bw[src]), written in place to g_h1 (fp32).
__global__ __launch_bounds__(256) void k_agg3() {
    int gid = blockIdx.x * 256 + threadIdx.x;
    if (gid >= NN * 8) return;
    int n = gid >> 3;
    int j = gid & 7;
    int p   = g_off[n];
    int end = g_off[n + 1];
    float2 acc[20];
#pragma unroll
    for (int i = 0; i < 20; i++) acc[i] = make_float2(0.f, 0.f);
    if (p < end) {
        int2 ed = g_epack[p];
        for (;;) {
            int   s = ed.x;
            float w = __int_as_float(ed.y);
            p++;
            bool more = (p < end);
            if (more) ed = g_epack[p];           // prefetch next record
            const uint4* src = (const uint4*)(g_bwh + (size_t)s * ROW) + j;
#pragma unroll
            for (int i = 0; i < 5; i++) {
                uint4 u = src[8 * i];
                float2 f0 = __half22float2(u32_as_h2(u.x));
                float2 f1 = __half22float2(u32_as_h2(u.y));
                float2 f2 = __half22float2(u32_as_h2(u.z));
                float2 f3 = __half22float2(u32_as_h2(u.w));
                acc[4*i+0].x = fmaf(w, f0.x, acc[4*i+0].x);
                acc[4*i+0].y = fmaf(w, f0.y, acc[4*i+0].y);
                acc[4*i+1].x = fmaf(w, f1.x, acc[4*i+1].x);
                acc[4*i+1].y = fmaf(w, f1.y, acc[4*i+1].y);
                acc[4*i+2].x = fmaf(w, f2.x, acc[4*i+2].x);
                acc[4*i+2].y = fmaf(w, f2.y, acc[4*i+2].y);
                acc[4*i+3].x = fmaf(w, f3.x, acc[4*i+3].x);
                acc[4*i+3].y = fmaf(w, f3.y, acc[4*i+3].y);
            }
            if (!more) break;
        }
    }
    // Epilogue: half-chunk c = j + 8i covers fp32 float4s 2c and 2c+1.
    float4* an = (float4*)(g_h1 + (size_t)n * ROW);
#pragma unroll
    for (int i = 0; i < 5; i++) {
        int c = j + 8 * i;
        float4 t0 = an[2 * c];
        float4 t1 = an[2 * c + 1];
        t0.x = fmaxf(t0.x + acc[4*i+0].x, 0.f);
        t0.y = fmaxf(t0.y + acc[4*i+0].y, 0.f);
        t0.z = fmaxf(t0.z + acc[4*i+1].x, 0.f);
        t0.w = fmaxf(t0.w + acc[4*i+1].y, 0.f);
        t1.x = fmaxf(t1.x + acc[4*i+2].x, 0.f);
        t1.y = fmaxf(t1.y + acc[4*i+2].y, 0.f);
        t1.z = fmaxf(t1.z + acc[4*i+3].x, 0.f);
        t1.w = fmaxf(t1.w + acc[4*i+3].y, 0.f);
        an[2 * c] = t0;
        an[2 * c + 1] = t1;
    }
}

// Stage 4: temporal conv 2 (GLU 16->16) + mean over t + linear, fused.
// 8 threads per (b, n); thread p owns channels 2p, 2p+1. x via LDG.128.
__global__ __launch_bounds__(256) void k_stage4(
    const float* __restrict__ wP, const float* __restrict__ bP,
    const float* __restrict__ wQ, const float* __restrict__ bQ,
    const float* __restrict__ wR, const float* __restrict__ bR,
    const float* __restrict__ lw, const float* __restrict__ lb,
    float* __restrict__ out) {
    __shared__ float sWP[768], sWQ[768], sWR[768];  // [k][c][h]
    __shared__ float sBP[16], sBQ[16], sBR[16], sLW[32], sLB[2];
    int tid = threadIdx.x;
    for (int i = tid; i < 768; i += 256) {
        sWP[i] = wP[i];
        sWQ[i] = wQ[i];
        sWR[i] = wR[i];
    }
    if (tid < 16) { sBP[tid] = bP[tid]; sBQ[tid] = bQ[tid]; sBR[tid] = bR[tid]; }
    if (tid < 32) sLW[tid] = lw[tid];
    if (tid < 2)  sLB[tid] = lb[tid];
    __syncthreads();

    int gid = blockIdx.x * 256 + tid;        // exactly BB*NN*8 = 800000 threads
    int g = gid >> 3;                        // (b, n) group
    int p = gid & 7;                         // channel pair
    int b = g / NN;
    int n = g - b * NN;
    const float* row = g_h1 + (size_t)n * ROW + b * (T1 * HH);
    int h0 = 2 * p, h1 = 2 * p + 1;

    float bp0 = sBP[h0], bp1 = sBP[h1];
    float bq0 = sBQ[h0], bq1 = sBQ[h1];
    float br0 = sBR[h0], br1 = sBR[h1];
    float m0 = 0.f, m1 = 0.f;

#define FMA6(xv, kc)                                              \
    {                                                             \
        P0 = fmaf(xv, sWP[(kc) * 16 + h0], P0);                   \
        P1 = fmaf(xv, sWP[(kc) * 16 + h1], P1);                   \
        Q0 = fmaf(xv, sWQ[(kc) * 16 + h0], Q0);                   \
        Q1 = fmaf(xv, sWQ[(kc) * 16 + h1], Q1);                   \
        R0 = fmaf(xv, sWR[(kc) * 16 + h0], R0);                   \
        R1 = fmaf(xv, sWR[(kc) * 16 + h1], R1);                   \
    }
#define FMA6x4(base, V) FMA6(V.x, base) FMA6(V.y, (base)+1)       \
                        FMA6(V.z, (base)+2) FMA6(V.w, (base)+3)

#pragma unroll 1
    for (int t = 0; t < T2; t++) {
        const float4* x4 = (const float4*)(row + t * HH);  // 48 contiguous floats
        float4 v0 = x4[0], v1 = x4[1], v2  = x4[2],  v3  = x4[3];
        float4 v4 = x4[4], v5 = x4[5], v6  = x4[6],  v7  = x4[7];
        float4 v8 = x4[8], v9 = x4[9], v10 = x4[10], v11 = x4[11];
        float P0 = bp0, P1 = bp1, Q0 = bq0, Q1 = bq1, R0 = br0, R1 = br1;
        FMA6x4(0,  v0) FMA6x4(4,  v1) FMA6x4(8,  v2)  FMA6x4(12, v3)
        FMA6x4(16, v4) FMA6x4(20, v5) FMA6x4(24, v6)  FMA6x4(28, v7)
        FMA6x4(32, v8) FMA6x4(36, v9) FMA6x4(40, v10) FMA6x4(44, v11)
        float s0 = 1.f / (1.f + __expf(-Q0));
        float s1 = 1.f / (1.f + __expf(-Q1));
        m0 += fmaxf(fmaf(P0, s0, R0), 0.f);
        m1 += fmaxf(fmaf(P1, s1, R1), 0.f);
    }
#undef FMA6x4
#undef FMA6

    m0 *= 0.125f;
    m1 *= 0.125f;
    float o0 = m0 * sLW[2 * h0]     + m1 * sLW[2 * h1];
    float o1 = m0 * sLW[2 * h0 + 1] + m1 * sLW[2 * h1 + 1];
#pragma unroll
    for (int s = 4; s > 0; s >>= 1) {
        o0 += __shfl_down_sync(0xFFFFFFFFu, o0, s, 8);
        o1 += __shfl_down_sync(0xFFFFFFFFu, o1, s, 8);
    }
    if (p == 0) ((float2*)out)[g] = make_float2(o0 + sLB[0], o1 + sLB[1]);
}

// ---------------------------------------------------------------------------
extern "C" void kernel_launch(void* const* d_in, const int* in_sizes, int n_in,
                              void* d_out, int out_size) {
    const float* x   = (const float*)d_in[0];
    const int*   eiw = (const int*)d_in[1];   // edge_index words (int32 or int64)
    const float* ew  = (const float*)d_in[2];
    const float* tc1Pw = (const float*)d_in[3];
    const float* tc1Pb = (const float*)d_in[4];
    const float* tc1Qw = (const float*)d_in[5];
    const float* tc1Qb = (const float*)d_in[6];
    const float* tc1Rw = (const float*)d_in[7];
    const float* tc1Rb = (const float*)d_in[8];
    const float* tc2Pw = (const float*)d_in[9];
    const float* tc2Pb = (const float*)d_in[10];
    const float* tc2Qw = (const float*)d_in[11];
    const float* tc2Qb = (const float*)d_in[12];
    const float* tc2Rw = (const float*)d_in[13];
    const float* tc2Rb = (const float*)d_in[14];
    const float* chebw = (const float*)d_in[15];
    const float* chebb = (const float*)d_in[16];
    const float* linw  = (const float*)d_in[17];
    const float* linb  = (const float*)d_in[18];
    float* out = (float*)d_out;

    k_init<<<(NN + 255) / 256, 256>>>();
    k_detect<<<16, 256>>>(eiw);
    k_convert<<<(EE + 255) / 256, 256>>>(eiw, ew);
    k_scan_part<<<NB, 256>>>();
    k_scan_top<<<1, 256>>>();
    k_scan_add_dis<<<(NN + 255) / 256, 256>>>();
    k_scatter<<<(EE + 255) / 256, 256>>>(ew);
    k_stage1<<<(BT1 * NN + 255) / 256, 256>>>(x, tc1Pw, tc1Pb, tc1Qw, tc1Qb, tc1Rw, tc1Rb,
                                              chebw, chebb);
    k_agg3<<<(NN * 8 + 255) / 256, 256>>>();
    k_stage4<<<(BB * NN * 8) / 256, 256>>>(tc2Pw, tc2Pb, tc2Qw, tc2Qb, tc2Rw, tc2Rb,
                                           linw, linb, out);
}

// round 16
// speedup vs baseline: 3.3750x; 1.0646x over previous
#include <cuda_runtime.h>
#include <cuda_fp16.h>
#include <cuda_bf16.h>

// Problem constants
#define NN 50000
#define EE 800000
#define BB 2
#define TT 12
#define HH 16
#define T1 10          // T-2
#define T2 8           // T-4
#define BT1 (BB*T1)    // 20
#define ROW (BT1*HH)   // 320 floats per node
#define NB  ((NN + 255) / 256)   // scan blocks = 196

// Bit-cast helpers (the named intrinsics don't exist in cuda_fp16.h)
__device__ __forceinline__ unsigned h2_as_u32(__half2 h) {
    return *reinterpret_cast<unsigned*>(&h);
}
__device__ __forceinline__ __half2 u32_as_h2(unsigned u) {
    return *reinterpret_cast<__half2*>(&u);
}

// Scratch (node-major layout: [n][b][t][h]).
// g_h1: holds A = h1@W0 + b after stage1, then h2 (in place) after agg.
// g_bwh: holds Bw = h1@W1 in fp16 after stage1 (gather source, 32 MB, L2-resident).
__device__ float  g_h1[(size_t)NN * ROW];
__device__ __half g_bwh[(size_t)NN * ROW];
__device__ float  g_deg[NN];
__device__ float  g_dis[NN];
__device__ int    g_src[EE];
__device__ int    g_dst[EE];
__device__ int    g_cnt[NN];       // in-degree (by dst)
__device__ int    g_exc[NN];       // block-local exclusive scan
__device__ int    g_bsum[NB];      // per-block sums -> exclusive scanned
__device__ int    g_off[NN + 1];   // CSR row offsets (by dst)
__device__ int    g_fill[NN];      // bump cursors for scatter
__device__ int2   g_epack[EE];     // {src, norm-bits} sorted by dst
__device__ int    g_oddnz;         // >0 => edge_index is int32; ==0 => int64

// Two identical repeat macros so they can nest.
#define RPT16A(M) M(0) M(1) M(2) M(3) M(4) M(5) M(6) M(7) \
                  M(8) M(9) M(10) M(11) M(12) M(13) M(14) M(15)
#define RPT16B(M) M(0) M(1) M(2) M(3) M(4) M(5) M(6) M(7) \
                  M(8) M(9) M(10) M(11) M(12) M(13) M(14) M(15)

// ---------------------------------------------------------------------------
__global__ void k_init() {
    int i = blockIdx.x * blockDim.x + threadIdx.x;
    if (i == 0) g_oddnz = 0;
    if (i < NN) { g_deg[i] = 0.f; g_cnt[i] = 0; }
}

// Detect dtype of edge_index (odd int32 words all zero <=> int64).
__global__ void k_detect(const int* __restrict__ w) {
    int i = blockIdx.x * blockDim.x + threadIdx.x;   // 4096 threads
    int v = w[2 * i + 1];
    unsigned ballot = __ballot_sync(0xFFFFFFFFu, v != 0);
    if ((threadIdx.x & 31) == 0 && ballot) atomicAdd(&g_oddnz, __popc(ballot));
}

// Unpack src/dst, accumulate weighted degree (by src) and in-count (by dst)
__global__ void k_convert(const int* __restrict__ w, const float* __restrict__ ew) {
    int e = blockIdx.x * blockDim.x + threadIdx.x;
    if (e >= EE) return;
    int src, dst;
    if (g_oddnz == 0) {  // int64
        src = w[2 * e];
        dst = w[2 * EE + 2 * e];
    } else {             // int32
        src = w[e];
        dst = w[EE + e];
    }
    g_src[e] = src;
    g_dst[e] = dst;
    atomicAdd(&g_deg[src], ew[e]);
    atomicAdd(&g_cnt[dst], 1);
}

// Scan pass 1: per-block exclusive scan of cnt, emit block sums
__global__ void k_scan_part() {
    __shared__ int s[256];
    int tid = threadIdx.x;
    int i = blockIdx.x * 256 + tid;
    int v = (i < NN) ? g_cnt[i] : 0;
    s[tid] = v;
    __syncthreads();
#pragma unroll
    for (int d = 1; d < 256; d <<= 1) {
        int t = (tid >= d) ? s[tid - d] : 0;
        __syncthreads();
        s[tid] += t;
        __syncthreads();
    }
    if (i < NN) g_exc[i] = s[tid] - v;
    if (tid == 255) g_bsum[blockIdx.x] = s[255];
}

// Scan pass 2: exclusive scan of block sums (single block)
__global__ void k_scan_top() {
    __shared__ int s[256];
    int tid = threadIdx.x;
    int v = (tid < NB) ? g_bsum[tid] : 0;
    s[tid] = v;
    __syncthreads();
#pragma unroll
    for (int d = 1; d < 256; d <<= 1) {
        int t = (tid >= d) ? s[tid - d] : 0;
        __syncthreads();
        s[tid] += t;
        __syncthreads();
    }
    if (tid < NB) g_bsum[tid] = s[tid] - v;
}

// Scan pass 3: final offsets + fill cursors + dis (merged)
__global__ void k_scan_add_dis() {
    int i = blockIdx.x * blockDim.x + threadIdx.x;
    if (i >= NN) return;
    int o = g_exc[i] + g_bsum[i >> 8];
    g_off[i] = o;
    g_fill[i] = o;
    if (i == 0) g_off[NN] = EE;
    float d = g_deg[i];
    g_dis[i] = (d > 0.f) ? rsqrtf(fmaxf(d, 1e-12f)) : 0.f;
}

// Scatter: CSR-sorted packed (src, norm) by dst
__global__ void k_scatter(const float* __restrict__ ew) {
    int e = blockIdx.x * blockDim.x + threadIdx.x;
    if (e >= EE) return;
    int src = g_src[e];
    int dst = g_dst[e];
    float nrm = -g_dis[src] * ew[e] * g_dis[dst];
    int pos = atomicAdd(&g_fill[dst], 1);
    g_epack[pos] = make_int2(src, __float_as_int(nrm));
}

// Stage 1: temporal conv (GLU, 1->16) fused with the Cheb weight transforms.
// Writes A = h1@W0 + cb  -> g_h1   (fp32; combined in place by k_agg3)
//        Bw = h1@W1      -> g_bwh  (fp16 gather payload)
__global__ void k_stage1(const float* __restrict__ x,
                         const float* __restrict__ wP, const float* __restrict__ bP,
                         const float* __restrict__ wQ, const float* __restrict__ bQ,
                         const float* __restrict__ wR, const float* __restrict__ bR,
                         const float* __restrict__ cw, const float* __restrict__ cb) {
    __shared__ float sW0[256], sW1[256], sCB[16];
    {
        int tid = threadIdx.x;
        for (int i = tid; i < 256; i += blockDim.x) {
            sW0[i] = cw[i];
            sW1[i] = cw[256 + i];
        }
        if (tid < 16) sCB[tid] = cb[tid];
        __syncthreads();
    }
    int idx = blockIdx.x * blockDim.x + threadIdx.x;
    if (idx >= BT1 * NN) return;
    int n  = idx / BT1;
    int bt = idx - n * BT1;
    int b  = bt / T1;
    int t  = bt - b * T1;
    const float* xb = x + (size_t)(b * TT + t) * NN + n;
    float x0 = __ldg(xb);
    float x1 = __ldg(xb + NN);
    float x2 = __ldg(xb + 2 * NN);

#define S1H(h)                                                                  \
    float v##h;                                                                 \
    {                                                                           \
        float P = bP[h] + x0 * wP[h] + x1 * wP[16 + h] + x2 * wP[32 + h];       \
        float Q = bQ[h] + x0 * wQ[h] + x1 * wQ[16 + h] + x2 * wQ[32 + h];       \
        float R = bR[h] + x0 * wR[h] + x1 * wR[16 + h] + x2 * wR[32 + h];       \
        float s = __fdividef(1.f, 1.f + __expf(-Q));                            \
        v##h = fmaxf(fmaf(P, s, R), 0.f);                                       \
    }
    RPT16A(S1H)
#undef S1H

#define DECL(h) float a##h = sCB[h]; float g##h = 0.f;
    RPT16A(DECL)
#undef DECL

#define ACC(h) a##h = fmaf(vc, w0[h], a##h); g##h = fmaf(vc, w1[h], g##h);
#define STEP(c)                                                   \
    {                                                             \
        float vc = v##c;                                          \
        const float* w0 = &sW0[(c) * 16];                         \
        const float* w1 = &sW1[(c) * 16];                         \
        RPT16B(ACC)                                               \
    }
    RPT16A(STEP)
#undef STEP
#undef ACC

    float4* oa = (float4*)(g_h1 + (size_t)n * ROW + bt * HH);
    oa[0] = make_float4(a0, a1, a2, a3);
    oa[1] = make_float4(a4, a5, a6, a7);
    oa[2] = make_float4(a8, a9, a10, a11);
    oa[3] = make_float4(a12, a13, a14, a15);

    // Pack Bw to fp16: 16 halves = 2 uint4 stores.
    unsigned p0 = h2_as_u32(__floats2half2_rn(g0,  g1));
    unsigned p1 = h2_as_u32(__floats2half2_rn(g2,  g3));
    unsigned p2 = h2_as_u32(__floats2half2_rn(g4,  g5));
    unsigned p3 = h2_as_u32(__floats2half2_rn(g6,  g7));
    unsigned p4 = h2_as_u32(__floats2half2_rn(g8,  g9));
    unsigned p5 = h2_as_u32(__floats2half2_rn(g10, g11));
    unsigned p6 = h2_as_u32(__floats2half2_rn(g12, g13));
    unsigned p7 = h2_as_u32(__floats2half2_rn(g14, g15));
    uint4* og = (uint4*)(g_bwh + (size_t)n * ROW + bt * HH);  // uint4 idx n*40 + bt*2
    og[0] = make_uint4(p0, p1, p2, p3);
    og[1] = make_uint4(p4, p5, p6, p7);
}

// CSR aggregation + Cheb combine epilogue.  8 threads per dst node.
// Row = 320 halves = 40 uint4; thread j owns uint4 chunks {j, j+8, ..., j+32} (5).
// fp16 payload unpacked to fp32 and accumulated in fp32.
// h2[n] = relu(A[n] + sum norm * Bw[src]), written in place to g_h1 (fp32).
__global__ __launch_bounds__(256) void k_agg3() {
    int gid = blockIdx.x * 256 + threadIdx.x;
    if (gid >= NN * 8) return;
    int n = gid >> 3;
    int j = gid & 7;
    int p   = g_off[n];
    int end = g_off[n + 1];
    float2 acc[20];
#pragma unroll
    for (int i = 0; i < 20; i++) acc[i] = make_float2(0.f, 0.f);
    if (p < end) {
        int2 ed = g_epack[p];
        for (;;) {
            int   s = ed.x;
            float w = __int_as_float(ed.y);
            p++;
            bool more = (p < end);
            if (more) ed = g_epack[p];           // prefetch next record
            const uint4* src = (const uint4*)(g_bwh + (size_t)s * ROW) + j;
#pragma unroll
            for (int i = 0; i < 5; i++) {
                uint4 u = src[8 * i];
                float2 f0 = __half22float2(u32_as_h2(u.x));
                float2 f1 = __half22float2(u32_as_h2(u.y));
                float2 f2 = __half22float2(u32_as_h2(u.z));
                float2 f3 = __half22float2(u32_as_h2(u.w));
                acc[4*i+0].x = fmaf(w, f0.x, acc[4*i+0].x);
                acc[4*i+0].y = fmaf(w, f0.y, acc[4*i+0].y);
                acc[4*i+1].x = fmaf(w, f1.x, acc[4*i+1].x);
                acc[4*i+1].y = fmaf(w, f1.y, acc[4*i+1].y);
                acc[4*i+2].x = fmaf(w, f2.x, acc[4*i+2].x);
                acc[4*i+2].y = fmaf(w, f2.y, acc[4*i+2].y);
                acc[4*i+3].x = fmaf(w, f3.x, acc[4*i+3].x);
                acc[4*i+3].y = fmaf(w, f3.y, acc[4*i+3].y);
            }
            if (!more) break;
        }
    }
    // Epilogue: half-chunk c = j + 8i covers fp32 float4s 2c and 2c+1.
    float4* an = (float4*)(g_h1 + (size_t)n * ROW);
#pragma unroll
    for (int i = 0; i < 5; i++) {
        int c = j + 8 * i;
        float4 t0 = an[2 * c];
        float4 t1 = an[2 * c + 1];
        t0.x = fmaxf(t0.x + acc[4*i+0].x, 0.f);
        t0.y = fmaxf(t0.y + acc[4*i+0].y, 0.f);
        t0.z = fmaxf(t0.z + acc[4*i+1].x, 0.f);
        t0.w = fmaxf(t0.w + acc[4*i+1].y, 0.f);
        t1.x = fmaxf(t1.x + acc[4*i+2].x, 0.f);
        t1.y = fmaxf(t1.y + acc[4*i+2].y, 0.f);
        t1.z = fmaxf(t1.z + acc[4*i+3].x, 0.f);
        t1.w = fmaxf(t1.w + acc[4*i+3].y, 0.f);
        an[2 * c] = t0;
        an[2 * c + 1] = t1;
    }
}

// Stage 4: temporal conv 2 (GLU 16->16) + mean over t + linear, fused.
// 8 threads per (b, n); thread p owns channels 2p, 2p+1 (adjacent -> float2 LDS).
__global__ __launch_bounds__(256) void k_stage4(
    const float* __restrict__ wP, const float* __restrict__ bP,
    const float* __restrict__ wQ, const float* __restrict__ bQ,
    const float* __restrict__ wR, const float* __restrict__ bR,
    const float* __restrict__ lw, const float* __restrict__ lb,
    float* __restrict__ out) {
    __shared__ float sWP[768], sWQ[768], sWR[768];  // [k][c][h]
    __shared__ float sBP[16], sBQ[16], sBR[16], sLW[32], sLB[2];
    int tid = threadIdx.x;
    for (int i = tid; i < 768; i += 256) {
        sWP[i] = wP[i];
        sWQ[i] = wQ[i];
        sWR[i] = wR[i];
    }
    if (tid < 16) { sBP[tid] = bP[tid]; sBQ[tid] = bQ[tid]; sBR[tid] = bR[tid]; }
    if (tid < 32) sLW[tid] = lw[tid];
    if (tid < 2)  sLB[tid] = lb[tid];
    __syncthreads();

    int gid = blockIdx.x * 256 + tid;        // exactly BB*NN*8 = 800000 threads
    int g = gid >> 3;                        // (b, n) group
    int p = gid & 7;                         // channel pair
    int b = g / NN;
    int n = g - b * NN;
    const float* row = g_h1 + (size_t)n * ROW + b * (T1 * HH);

    // float2 views: entry (kc)*8 + p is channels {2p, 2p+1} of step kc.
    const float2* wP2 = (const float2*)sWP + p;
    const float2* wQ2 = (const float2*)sWQ + p;
    const float2* wR2 = (const float2*)sWR + p;
    float2 bp2 = ((const float2*)sBP)[p];
    float2 bq2 = ((const float2*)sBQ)[p];
    float2 br2 = ((const float2*)sBR)[p];
    float m0 = 0.f, m1 = 0.f;

#define FMA6(xv, kc)                                              \
    {                                                             \
        float2 wp = wP2[(kc) * 8];                                \
        float2 wq = wQ2[(kc) * 8];                                \
        float2 wr = wR2[(kc) * 8];                                \
        P0 = fmaf(xv, wp.x, P0); P1 = fmaf(xv, wp.y, P1);         \
        Q0 = fmaf(xv, wq.x, Q0); Q1 = fmaf(xv, wq.y, Q1);         \
        R0 = fmaf(xv, wr.x, R0); R1 = fmaf(xv, wr.y, R1);         \
    }
#define FMA6x4(base, V) FMA6(V.x, base) FMA6(V.y, (base)+1)       \
                        FMA6(V.z, (base)+2) FMA6(V.w, (base)+3)

#pragma unroll 1
    for (int t = 0; t < T2; t++) {
        const float4* x4 = (const float4*)(row + t * HH);  // 48 contiguous floats
        float4 v0 = x4[0], v1 = x4[1], v2  = x4[2],  v3  = x4[3];
        float4 v4 = x4[4], v5 = x4[5], v6  = x4[6],  v7  = x4[7];
        float4 v8 = x4[8], v9 = x4[9], v10 = x4[10], v11 = x4[11];
        float P0 = bp2.x, P1 = bp2.y;
        float Q0 = bq2.x, Q1 = bq2.y;
        float R0 = br2.x, R1 = br2.y;
        FMA6x4(0,  v0) FMA6x4(4,  v1) FMA6x4(8,  v2)  FMA6x4(12, v3)
        FMA6x4(16, v4) FMA6x4(20, v5) FMA6x4(24, v6)  FMA6x4(28, v7)
        FMA6x4(32, v8) FMA6x4(36, v9) FMA6x4(40, v10) FMA6x4(44, v11)
        float s0 = __fdividef(1.f, 1.f + __expf(-Q0));
        float s1 = __fdividef(1.f, 1.f + __expf(-Q1));
        m0 += fmaxf(fmaf(P0, s0, R0), 0.f);
        m1 += fmaxf(fmaf(P1, s1, R1), 0.f);
    }
#undef FMA6x4
#undef FMA6

    m0 *= 0.125f;
    m1 *= 0.125f;
    int h0 = 2 * p, h1 = 2 * p + 1;
    float o0 = m0 * sLW[2 * h0]     + m1 * sLW[2 * h1];
    float o1 = m0 * sLW[2 * h0 + 1] + m1 * sLW[2 * h1 + 1];
#pragma unroll
    for (int s = 4; s > 0; s >>= 1) {
        o0 += __shfl_down_sync(0xFFFFFFFFu, o0, s, 8);
        o1 += __shfl_down_sync(0xFFFFFFFFu, o1, s, 8);
    }
    if (p == 0) ((float2*)out)[g] = make_float2(o0 + sLB[0], o1 + sLB[1]);
}

// ---------------------------------------------------------------------------
extern "C" void kernel_launch(void* const* d_in, const int* in_sizes, int n_in,
                              void* d_out, int out_size) {
    const float* x   = (const float*)d_in[0];
    const int*   eiw = (const int*)d_in[1];   // edge_index words (int32 or int64)
    const float* ew  = (const float*)d_in[2];
    const float* tc1Pw = (const float*)d_in[3];
    const float* tc1Pb = (const float*)d_in[4];
    const float* tc1Qw = (const float*)d_in[5];
    const float* tc1Qb = (const float*)d_in[6];
    const float* tc1Rw = (const float*)d_in[7];
    const float* tc1Rb = (const float*)d_in[8];
    const float* tc2Pw = (const float*)d_in[9];
    const float* tc2Pb = (const float*)d_in[10];
    const float* tc2Qw = (const float*)d_in[11];
    const float* tc2Qb = (const float*)d_in[12];
    const float* tc2Rw = (const float*)d_in[13];
    const float* tc2Rb = (const float*)d_in[14];
    const float* chebw = (const float*)d_in[15];
    const float* chebb = (const float*)d_in[16];
    const float* linw  = (const float*)d_in[17];
    const float* linb  = (const float*)d_in[18];
    float* out = (float*)d_out;

    k_init<<<(NN + 255) / 256, 256>>>();
    k_detect<<<16, 256>>>(eiw);
    k_convert<<<(EE + 255) / 256, 256>>>(eiw, ew);
    k_scan_part<<<NB, 256>>>();
    k_scan_top<<<1, 256>>>();
    k_scan_add_dis<<<(NN + 255) / 256, 256>>>();
    k_scatter<<<(EE + 255) / 256, 256>>>(ew);
    k_stage1<<<(BT1 * NN + 255) / 256, 256>>>(x, tc1Pw, tc1Pb, tc1Qw, tc1Qb, tc1Rw, tc1Rb,
                                              chebw, chebb);
    k_agg3<<<(NN * 8 + 255) / 256, 256>>>();
    k_stage4<<<(BB * NN * 8) / 256, 256>>>(tc2Pw, tc2Pb, tc2Qw, tc2Qb, tc2Rw, tc2Rb,
                                           linw, linb, out);
}